// round 6
// baseline (speedup 1.0000x reference)
#include <cuda_runtime.h>
#include <math.h>

#define BATCH 8192
#define W 256
#define KCHUNK 256
#define NKCH  (BATCH / KCHUNK)       // 32
#define NPAIR 10
#define NCB   64
#define ROWS_PER_CB (BATCH / NCB)    // 128

// Device scratch (no allocations allowed).
__device__ float g_G[W * W];          // Gram accumulator (upper tile-pairs valid)
__device__ float g_colsum[NCB][W];    // partial column sums
__device__ float g_sumsq;             // scalar accumulator for ||D||^2

// Upper-triangular 64x64 tile-pair enumeration: (ti, tj) with ti <= tj.
__constant__ int c_ti[NPAIR] = {0,0,0,0,1,1,1,2,2,3};
__constant__ int c_tj[NPAIR] = {0,1,2,3,1,2,3,2,3,3};

// ---- f32x2 packed-FMA helpers (sm_100+; FFMA2 in SASS) ----------------------
__device__ __forceinline__ unsigned long long dup_f32(float a) {
    unsigned long long r;
    asm("mov.b64 %0, {%1, %1};" : "=l"(r) : "f"(a));
    return r;
}
__device__ __forceinline__ unsigned long long pack_f32(float lo, float hi) {
    unsigned long long r;
    asm("mov.b64 %0, {%1, %2};" : "=l"(r) : "f"(lo), "f"(hi));
    return r;
}
__device__ __forceinline__ void fma2(unsigned long long &acc,
                                     unsigned long long a, unsigned long long b) {
    asm("fma.rn.f32x2 %0, %1, %2, %0;" : "+l"(acc) : "l"(a), "l"(b));
}
__device__ __forceinline__ float2 unpack_f32x2(unsigned long long v) {
    float lo, hi;
    asm("mov.b64 {%0, %1}, %2;" : "=f"(lo), "=f"(hi) : "l"(v));
    return make_float2(lo, hi);
}

// ---------------------------------------------------------------------------
// Z: zero Gram accumulator + sumsq scalar (graph replays; must re-zero)
// ---------------------------------------------------------------------------
__global__ void zero_kernel() {
    int i = blockIdx.x * 256 + threadIdx.x;
    g_G[i] = 0.0f;                    // grid exactly covers W*W
    if (i == 0) g_sumsq = 0.0f;
}

// ---------------------------------------------------------------------------
// K1: partial column sums. 64 blocks x 256 threads, coalesced.
// ---------------------------------------------------------------------------
__global__ void colsum_kernel(const float* __restrict__ E) {
    int j = threadIdx.x;
    int b = blockIdx.x;
    const float* p = E + (size_t)b * ROWS_PER_CB * W + j;
    float s = 0.0f;
    #pragma unroll 8
    for (int r = 0; r < ROWS_PER_CB; ++r) s += p[(size_t)r * W];
    g_colsum[b][j] = s;
}

// ---------------------------------------------------------------------------
// K2: Gram, symmetric tiles only. Grid (10, 32): pair x K-chunk.
// 256 threads as 16x16; 4x4 micro-tile; f32x2 packed accumulation.
// ---------------------------------------------------------------------------
__global__ void gram_kernel(const float* __restrict__ E) {
    __shared__ float As[32][64];
    __shared__ float Bs[32][64];

    const int tid = threadIdx.x;
    const int tx  = tid & 15;         // i micro index
    const int ty  = tid >> 4;         // j micro index
    const int i0  = c_ti[blockIdx.x] * 64;
    const int j0  = c_tj[blockIdx.x] * 64;
    const int k0  = blockIdx.y * KCHUNK;

    unsigned long long acc2[4][2];    // [ia][j-pair]
    #pragma unroll
    for (int ia = 0; ia < 4; ++ia)
        #pragma unroll
        for (int jb = 0; jb < 2; ++jb) acc2[ia][jb] = 0ull;

    for (int kc = 0; kc < KCHUNK; kc += 32) {
        // Stage 32 rows x 64 cols for both operand column blocks.
        #pragma unroll
        for (int p = 0; p < 2; ++p) {
            int idx = p * 256 + tid;
            int row = idx >> 4;
            int f   = idx & 15;
            size_t base = (size_t)(k0 + kc + row) * W;
            ((float4*)As[row])[f] = ((const float4*)(E + base + i0))[f];
            ((float4*)Bs[row])[f] = ((const float4*)(E + base + j0))[f];
        }
        __syncthreads();

        #pragma unroll
        for (int kk = 0; kk < 32; ++kk) {
            float4 a = ((const float4*)As[kk])[tx];
            float4 b = ((const float4*)Bs[kk])[ty];
            unsigned long long b01 = pack_f32(b.x, b.y);
            unsigned long long b23 = pack_f32(b.z, b.w);
            unsigned long long a0 = dup_f32(a.x);
            unsigned long long a1 = dup_f32(a.y);
            unsigned long long a2 = dup_f32(a.z);
            unsigned long long a3 = dup_f32(a.w);
            fma2(acc2[0][0], a0, b01);  fma2(acc2[0][1], a0, b23);
            fma2(acc2[1][0], a1, b01);  fma2(acc2[1][1], a1, b23);
            fma2(acc2[2][0], a2, b01);  fma2(acc2[2][1], a2, b23);
            fma2(acc2[3][0], a3, b01);  fma2(acc2[3][1], a3, b23);
        }
        __syncthreads();
    }

    #pragma unroll
    for (int ia = 0; ia < 4; ++ia) {
        int gi = i0 + tx * 4 + ia;
        #pragma unroll
        for (int jb = 0; jb < 2; ++jb) {
            float2 v = unpack_f32x2(acc2[ia][jb]);
            int gj = j0 + ty * 4 + jb * 2;
            atomicAdd(&g_G[gi * W + gj + 0], v.x);
            atomicAdd(&g_G[gi * W + gj + 1], v.y);
        }
    }
}

// ---------------------------------------------------------------------------
// K3: parallel epilogue. 128 blocks x 256 threads.
// Block b handles rows b and 255-b (257 upper-tri entries -> balanced).
// ||D||^2 = sum_diag D_ii^2 + 2 * sum_{j>i} D_ij^2 ; atomicAdd partials.
// ---------------------------------------------------------------------------
__global__ void finalize_partial() {
    __shared__ float mu[W];
    __shared__ float red[256];

    const int t = threadIdx.x;

    // Redundant per-block mean reduction (cheap: 64KB from L2).
    float s = 0.0f;
    #pragma unroll 8
    for (int b = 0; b < NCB; ++b) s += g_colsum[b][t];
    mu[t] = s * (1.0f / BATCH);
    __syncthreads();

    const float invB = 1.0f / BATCH;
    float acc = 0.0f;
    int rows[2] = {(int)blockIdx.x, (W - 1) - (int)blockIdx.x};
    #pragma unroll
    for (int r = 0; r < 2; ++r) {
        int i = rows[r];
        int j = i + t;                 // only upper triangle j >= i
        if (j < W) {
            float d = g_G[i * W + j] * invB - mu[i] * mu[j] - (j == i ? 1.0f : 0.0f);
            acc += (j == i ? 1.0f : 2.0f) * d * d;
        }
    }

    red[t] = acc;
    __syncthreads();
    for (int st = 128; st > 0; st >>= 1) {
        if (t < st) red[t] += red[t + st];
        __syncthreads();
    }
    if (t == 0) atomicAdd(&g_sumsq, red[0]);
}

// ---------------------------------------------------------------------------
__global__ void sqrt_kernel(float* __restrict__ out) {
    out[0] = sqrtf(g_sumsq);
}

// ---------------------------------------------------------------------------
extern "C" void kernel_launch(void* const* d_in, const int* in_sizes, int n_in,
                              void* d_out, int out_size) {
    const float* E = (const float*)d_in[0];   // [8192, 256] fp32
    float* out = (float*)d_out;

    zero_kernel<<<W * W / 256, 256>>>();
    colsum_kernel<<<NCB, 256>>>(E);
    gram_kernel<<<dim3(NPAIR, NKCH), 256>>>(E);
    finalize_partial<<<W / 2, 256>>>();
    sqrt_kernel<<<1, 1>>>(out);
}